// round 1
// baseline (speedup 1.0000x reference)
#include <cuda_runtime.h>
#include <cuda_bf16.h>
#include <math.h>

// Problem constants
#define BATCH 32
#define NNODE 1024
#define FEAT  256           // IN_F == OUT_F == 256
#define MROWS (BATCH*NNODE) // 32768
#define ALPHA_LRELU 0.2f
#define NEG_INF_F  (-9.0e15f)

// ---------------- scratch (device globals; no runtime allocation) -----------
__device__ float g_Wh[(size_t)MROWS * FEAT];                 // 32 MB
__device__ float g_si[MROWS];
__device__ float g_sj[MROWS];
__device__ float g_attn[(size_t)BATCH * NNODE * NNODE];      // 128 MB

// ============================================================================
// K1: Wh[m,o] = sum_k h[m,k] * W[o,k]   (NT GEMM, M=32768, N=256, K=256)
// 128x128 block tile, 8x8 register tile, BK=16
// ============================================================================
__global__ __launch_bounds__(256) void k_wh(const float* __restrict__ A,
                                            const float* __restrict__ Bw)
{
    __shared__ float sA[16][132];
    __shared__ float sB[16][132];

    const int m0 = blockIdx.y * 128;
    const int n0 = blockIdx.x * 128;
    const int tid = threadIdx.x;
    const int ty = tid >> 4;      // 0..15
    const int tx = tid & 15;      // 0..15

    float acc[8][8];
#pragma unroll
    for (int i = 0; i < 8; i++)
#pragma unroll
        for (int j = 0; j < 8; j++) acc[i][j] = 0.f;

    for (int k0 = 0; k0 < FEAT; k0 += 16) {
        // Load A tile (128x16) and B tile (128x16), transpose into smem [k][m]
#pragma unroll
        for (int it = 0; it < 2; it++) {
            int f   = tid + it * 256;      // float4 id 0..511
            int row = f >> 2;
            int c4  = (f & 3) * 4;
            float4 v = *(const float4*)(A  + (size_t)(m0 + row) * FEAT + k0 + c4);
            sA[c4 + 0][row] = v.x; sA[c4 + 1][row] = v.y;
            sA[c4 + 2][row] = v.z; sA[c4 + 3][row] = v.w;
            float4 w = *(const float4*)(Bw + (size_t)(n0 + row) * FEAT + k0 + c4);
            sB[c4 + 0][row] = w.x; sB[c4 + 1][row] = w.y;
            sB[c4 + 2][row] = w.z; sB[c4 + 3][row] = w.w;
        }
        __syncthreads();

#pragma unroll
        for (int kk = 0; kk < 16; kk++) {
            float a[8], b[8];
            *(float4*)(a    ) = *(const float4*)&sA[kk][ty * 8];
            *(float4*)(a + 4) = *(const float4*)&sA[kk][ty * 8 + 4];
            *(float4*)(b    ) = *(const float4*)&sB[kk][tx * 8];
            *(float4*)(b + 4) = *(const float4*)&sB[kk][tx * 8 + 4];
#pragma unroll
            for (int i = 0; i < 8; i++)
#pragma unroll
                for (int j = 0; j < 8; j++) acc[i][j] += a[i] * b[j];
        }
        __syncthreads();
    }

#pragma unroll
    for (int i = 0; i < 8; i++) {
        int m = m0 + ty * 8 + i;
        float4* dst = (float4*)(g_Wh + (size_t)m * FEAT + n0 + tx * 8);
        dst[0] = make_float4(acc[i][0], acc[i][1], acc[i][2], acc[i][3]);
        dst[1] = make_float4(acc[i][4], acc[i][5], acc[i][6], acc[i][7]);
    }
}

// ============================================================================
// K2: si = Wh @ a1, sj = Wh @ a2  (one warp per row)
// ============================================================================
__global__ __launch_bounds__(256) void k_sisj(const float* __restrict__ a)
{
    int row  = blockIdx.x * 8 + (threadIdx.x >> 5);
    int lane = threadIdx.x & 31;
    const float* w = g_Wh + (size_t)row * FEAT;
    float d1 = 0.f, d2 = 0.f;
#pragma unroll
    for (int u = 0; u < 8; u++) {
        int k = lane + u * 32;
        float v = w[k];
        d1 += v * a[k];
        d2 += v * a[FEAT + k];
    }
#pragma unroll
    for (int s = 16; s > 0; s >>= 1) {
        d1 += __shfl_xor_sync(0xffffffff, d1, s);
        d2 += __shfl_xor_sync(0xffffffff, d2, s);
    }
    if (lane == 0) { g_si[row] = d1; g_sj[row] = d2; }
}

// ============================================================================
// K3: attention row softmax.
// attn[b,i,j] = softmax_j( mask(adj, leaky_relu(si[b,i] + sj[b,j])) )
// One block (256 threads) per (b,i) row; each thread covers 4 j.
// ============================================================================
__global__ __launch_bounds__(256) void k_softmax(const int* __restrict__ adj)
{
    const int row = blockIdx.x;               // b*N + i
    const int b   = row >> 10;
    const int tid = threadIdx.x;

    const int*   arow = adj  + (size_t)row * NNODE;
    const float* sjb  = g_sj + (size_t)b   * NNODE;
    const float  s_i  = g_si[row];

    float e[4];
    float mx = -INFINITY;
#pragma unroll
    for (int u = 0; u < 4; u++) {
        int j = tid + u * 256;
        float x = s_i + sjb[j];
        x = (x >= 0.f) ? x : ALPHA_LRELU * x;       // leaky_relu
        x = (arow[j] > 0) ? x : NEG_INF_F;          // mask
        e[u] = x;
        mx = fmaxf(mx, x);
    }

    __shared__ float red[256];
    red[tid] = mx;
    __syncthreads();
#pragma unroll
    for (int s = 128; s > 0; s >>= 1) {
        if (tid < s) red[tid] = fmaxf(red[tid], red[tid + s]);
        __syncthreads();
    }
    mx = red[0];
    __syncthreads();

    float sum = 0.f;
#pragma unroll
    for (int u = 0; u < 4; u++) {
        e[u] = __expf(e[u] - mx);
        sum += e[u];
    }
    red[tid] = sum;
    __syncthreads();
#pragma unroll
    for (int s = 128; s > 0; s >>= 1) {
        if (tid < s) red[tid] += red[tid + s];
        __syncthreads();
    }
    float inv = 1.f / red[0];

    float* out = g_attn + (size_t)row * NNODE;
#pragma unroll
    for (int u = 0; u < 4; u++)
        out[tid + u * 256] = e[u] * inv;
}

// ============================================================================
// K4: h_prime[b] = attn[b] (1024x1024) @ Wh[b] (1024x256), then ELU.
// NN GEMM: 128x128 block tile, 8x8 register tile, BK=16.
// grid = (2 o-blocks, 8 i-blocks, 32 batches)
// ============================================================================
__global__ __launch_bounds__(256) void k_out(float* __restrict__ out)
{
    __shared__ float sA[16][132];   // attn tile, transposed [k][i]
    __shared__ float sB[16][128];   // Wh tile, natural [k][o]

    const int b  = blockIdx.z;
    const int i0 = blockIdx.y * 128;
    const int o0 = blockIdx.x * 128;
    const int tid = threadIdx.x;
    const int ty = tid >> 4;
    const int tx = tid & 15;

    const float* A  = g_attn + (size_t)b * NNODE * NNODE;
    const float* Bm = g_Wh   + (size_t)b * NNODE * FEAT;

    float acc[8][8];
#pragma unroll
    for (int i = 0; i < 8; i++)
#pragma unroll
        for (int j = 0; j < 8; j++) acc[i][j] = 0.f;

    for (int k0 = 0; k0 < NNODE; k0 += 16) {
        // A tile: 128 i-rows x 16 k, transpose into sA[k][i]
#pragma unroll
        for (int it = 0; it < 2; it++) {
            int f   = tid + it * 256;   // 0..511
            int row = f >> 2;
            int c4  = (f & 3) * 4;
            float4 v = *(const float4*)(A + (size_t)(i0 + row) * NNODE + k0 + c4);
            sA[c4 + 0][row] = v.x; sA[c4 + 1][row] = v.y;
            sA[c4 + 2][row] = v.z; sA[c4 + 3][row] = v.w;
            // B tile: 16 k-rows x 128 o, natural layout
            int kr = f >> 5;            // 0..15
            int oc = (f & 31) * 4;      // 0..124
            float4 w = *(const float4*)(Bm + (size_t)(k0 + kr) * FEAT + o0 + oc);
            *(float4*)&sB[kr][oc] = w;
        }
        __syncthreads();

#pragma unroll
        for (int kk = 0; kk < 16; kk++) {
            float a[8], bb[8];
            *(float4*)(a     ) = *(const float4*)&sA[kk][ty * 8];
            *(float4*)(a  + 4) = *(const float4*)&sA[kk][ty * 8 + 4];
            *(float4*)(bb    ) = *(const float4*)&sB[kk][tx * 8];
            *(float4*)(bb + 4) = *(const float4*)&sB[kk][tx * 8 + 4];
#pragma unroll
            for (int i = 0; i < 8; i++)
#pragma unroll
                for (int j = 0; j < 8; j++) acc[i][j] += a[i] * bb[j];
        }
        __syncthreads();
    }

    // ELU epilogue + store
#pragma unroll
    for (int i = 0; i < 8; i++) {
        int m = b * NNODE + i0 + ty * 8 + i;
        float r[8];
#pragma unroll
        for (int j = 0; j < 8; j++) {
            float v = acc[i][j];
            r[j] = (v > 0.f) ? v : expm1f(v);
        }
        float4* dst = (float4*)(out + (size_t)m * FEAT + o0 + tx * 8);
        dst[0] = make_float4(r[0], r[1], r[2], r[3]);
        dst[1] = make_float4(r[4], r[5], r[6], r[7]);
    }
}

// ============================================================================
// launch
// ============================================================================
extern "C" void kernel_launch(void* const* d_in, const int* in_sizes, int n_in,
                              void* d_out, int out_size)
{
    const float* h   = (const float*)d_in[0];
    const int*   adj = (const int*)  d_in[1];
    const float* W   = (const float*)d_in[2];
    const float* a   = (const float*)d_in[3];
    float*       out = (float*)d_out;

    // K1: Wh = h @ W^T
    {
        dim3 grid(FEAT / 128, MROWS / 128);   // (2, 256)
        k_wh<<<grid, 256>>>(h, W);
    }
    // K2: si, sj
    {
        k_sisj<<<MROWS / 8, 256>>>(a);
    }
    // K3: masked leaky-relu softmax -> attn
    {
        k_softmax<<<MROWS, 256>>>(adj);
    }
    // K4: out = elu(attn @ Wh)
    {
        dim3 grid(FEAT / 128, NNODE / 128, BATCH);  // (2, 8, 32)
        k_out<<<grid, 256>>>(out);
    }
}

// round 2
// speedup vs baseline: 2.3207x; 2.3207x over previous
#include <cuda_runtime.h>
#include <cuda_bf16.h>
#include <math.h>
#include <stdint.h>

// Problem constants
#define BATCH 32
#define NNODE 1024
#define FEAT  256           // IN_F == OUT_F == 256
#define MROWS (BATCH*NNODE) // 32768
#define ALPHA_LRELU 0.2f
#define NEG_INF_F  (-9.0e15f)

// ---------------- scratch (device globals; no runtime allocation) -----------
__device__ float g_Wh[(size_t)MROWS * FEAT];                 // 32 MB (tf32-rounded)
__device__ float g_si[MROWS];
__device__ float g_sj[MROWS];
__device__ float g_attn[(size_t)BATCH * NNODE * NNODE];      // 128 MB (tf32-rounded)

// ---------------- helpers ----------------------------------------------------
__device__ __forceinline__ float to_tf32(float x) {
    float r;
    asm("cvt.rna.tf32.f32 %0, %1;" : "=f"(r) : "f"(x));
    return r;
}

__device__ __forceinline__ void cp16(uint32_t dst, const void* src) {
    asm volatile("cp.async.cg.shared.global [%0], [%1], 16;\n" :: "r"(dst), "l"(src));
}
__device__ __forceinline__ void cp_commit() {
    asm volatile("cp.async.commit_group;\n" ::);
}
__device__ __forceinline__ void cp_wait1() {
    asm volatile("cp.async.wait_group 1;\n" ::);
}
__device__ __forceinline__ void cp_wait0() {
    asm volatile("cp.async.wait_group 0;\n" ::);
}

__device__ __forceinline__ void mma_tf32(float* c, const uint32_t* a, const uint32_t* b) {
    asm volatile(
        "mma.sync.aligned.m16n8k8.row.col.f32.tf32.tf32.f32 "
        "{%0,%1,%2,%3}, {%4,%5,%6,%7}, {%8,%9}, {%0,%1,%2,%3};"
        : "+f"(c[0]), "+f"(c[1]), "+f"(c[2]), "+f"(c[3])
        : "r"(a[0]), "r"(a[1]), "r"(a[2]), "r"(a[3]), "r"(b[0]), "r"(b[1]));
}

// ============================================================================
// K1: Wh[m,o] = sum_k h[m,k] * W[o,k]   (NT GEMM, M=32768, N=256, K=256)
// tf32 mma, 128x128 CTA tile, BK=16, double-buffered cp.async.
// Both A (h) and B (W) are row-major over k -> store tiles as [row][k].
// Stores tf32-rounded values into g_Wh.
// ============================================================================
__global__ __launch_bounds__(256, 2) void k_wh_tc(const float* __restrict__ A,
                                                  const float* __restrict__ Bw)
{
    __shared__ float sA[2][128][20];
    __shared__ float sW[2][128][20];

    const int m0 = blockIdx.y * 128;
    const int n0 = blockIdx.x * 128;
    const int tid  = threadIdx.x;
    const int lane = tid & 31;
    const int wid  = tid >> 5;
    const int m0w  = (wid >> 2) * 64;   // 0 or 64
    const int n0w  = (wid & 3) * 32;    // 0,32,64,96

    float acc[4][4][4];
#pragma unroll
    for (int i = 0; i < 4; i++)
#pragma unroll
        for (int j = 0; j < 4; j++)
#pragma unroll
            for (int r = 0; r < 4; r++) acc[i][j][r] = 0.f;

    const int T = FEAT / 16;  // 16

    // stage loader
    auto load_stage = [&](int buf, int k0) {
#pragma unroll
        for (int it = 0; it < 2; it++) {
            int f   = tid + it * 256;    // 0..511
            int row = f >> 2;
            int kq  = (f & 3) * 4;
            cp16((uint32_t)__cvta_generic_to_shared(&sA[buf][row][kq]),
                 A + (size_t)(m0 + row) * FEAT + k0 + kq);
            cp16((uint32_t)__cvta_generic_to_shared(&sW[buf][row][kq]),
                 Bw + (size_t)(n0 + row) * FEAT + k0 + kq);
        }
    };

    load_stage(0, 0);
    cp_commit();

    for (int t = 0; t < T; t++) {
        if (t + 1 < T) { load_stage((t + 1) & 1, (t + 1) * 16); cp_commit(); }
        if (t + 1 < T) cp_wait1(); else cp_wait0();
        __syncthreads();

        const int buf = t & 1;
#pragma unroll
        for (int kk = 0; kk < 16; kk += 8) {
            uint32_t a[4][4];
#pragma unroll
            for (int mi = 0; mi < 4; mi++) {
                int r = m0w + mi * 16 + (lane >> 2);
                a[mi][0] = __float_as_uint(to_tf32(sA[buf][r    ][kk + (lane & 3)    ]));
                a[mi][1] = __float_as_uint(to_tf32(sA[buf][r + 8][kk + (lane & 3)    ]));
                a[mi][2] = __float_as_uint(to_tf32(sA[buf][r    ][kk + (lane & 3) + 4]));
                a[mi][3] = __float_as_uint(to_tf32(sA[buf][r + 8][kk + (lane & 3) + 4]));
            }
            uint32_t bf[4][2];
#pragma unroll
            for (int nj = 0; nj < 4; nj++) {
                int c = n0w + nj * 8 + (lane >> 2);
                bf[nj][0] = __float_as_uint(to_tf32(sW[buf][c][kk + (lane & 3)    ]));
                bf[nj][1] = __float_as_uint(to_tf32(sW[buf][c][kk + (lane & 3) + 4]));
            }
#pragma unroll
            for (int mi = 0; mi < 4; mi++)
#pragma unroll
                for (int nj = 0; nj < 4; nj++)
                    mma_tf32(acc[mi][nj], a[mi], bf[nj]);
        }
        __syncthreads();
    }

    // epilogue: round to tf32, store
#pragma unroll
    for (int mi = 0; mi < 4; mi++) {
#pragma unroll
        for (int nj = 0; nj < 4; nj++) {
            int row = m0 + m0w + mi * 16 + (lane >> 2);
            int col = n0 + n0w + nj * 8 + 2 * (lane & 3);
            float2 v0 = make_float2(to_tf32(acc[mi][nj][0]), to_tf32(acc[mi][nj][1]));
            float2 v1 = make_float2(to_tf32(acc[mi][nj][2]), to_tf32(acc[mi][nj][3]));
            *(float2*)(g_Wh + (size_t)row * FEAT + col)       = v0;
            *(float2*)(g_Wh + (size_t)(row + 8) * FEAT + col) = v1;
        }
    }
}

// ============================================================================
// K2: si = Wh @ a1, sj = Wh @ a2  (one warp per row)
// ============================================================================
__global__ __launch_bounds__(256) void k_sisj(const float* __restrict__ a)
{
    int row  = blockIdx.x * 8 + (threadIdx.x >> 5);
    int lane = threadIdx.x & 31;
    const float* w = g_Wh + (size_t)row * FEAT;
    float d1 = 0.f, d2 = 0.f;
#pragma unroll
    for (int u = 0; u < 8; u++) {
        int k = lane + u * 32;
        float v = w[k];
        d1 += v * a[k];
        d2 += v * a[FEAT + k];
    }
#pragma unroll
    for (int s = 16; s > 0; s >>= 1) {
        d1 += __shfl_xor_sync(0xffffffff, d1, s);
        d2 += __shfl_xor_sync(0xffffffff, d2, s);
    }
    if (lane == 0) { g_si[row] = d1; g_sj[row] = d2; }
}

// ============================================================================
// K3: attention row softmax -> tf32-rounded attn
// ============================================================================
__global__ __launch_bounds__(256) void k_softmax(const int* __restrict__ adj)
{
    const int row = blockIdx.x;               // b*N + i
    const int b   = row >> 10;
    const int tid = threadIdx.x;

    const int*   arow = adj  + (size_t)row * NNODE;
    const float* sjb  = g_sj + (size_t)b   * NNODE;
    const float  s_i  = g_si[row];

    float e[4];
    float mx = -INFINITY;
#pragma unroll
    for (int u = 0; u < 4; u++) {
        int j = tid + u * 256;
        float x = s_i + sjb[j];
        x = (x >= 0.f) ? x : ALPHA_LRELU * x;       // leaky_relu
        x = (arow[j] > 0) ? x : NEG_INF_F;          // mask
        e[u] = x;
        mx = fmaxf(mx, x);
    }

    __shared__ float red[256];
    red[tid] = mx;
    __syncthreads();
#pragma unroll
    for (int s = 128; s > 0; s >>= 1) {
        if (tid < s) red[tid] = fmaxf(red[tid], red[tid + s]);
        __syncthreads();
    }
    mx = red[0];
    __syncthreads();

    float sum = 0.f;
#pragma unroll
    for (int u = 0; u < 4; u++) {
        e[u] = __expf(e[u] - mx);
        sum += e[u];
    }
    red[tid] = sum;
    __syncthreads();
#pragma unroll
    for (int s = 128; s > 0; s >>= 1) {
        if (tid < s) red[tid] += red[tid + s];
        __syncthreads();
    }
    float inv = 1.f / red[0];

    float* out = g_attn + (size_t)row * NNODE;
#pragma unroll
    for (int u = 0; u < 4; u++)
        out[tid + u * 256] = to_tf32(e[u] * inv);
}

// ============================================================================
// K4: h_prime[b] = attn[b] (1024x1024) @ Wh[b] (1024x256), then ELU.
// tf32 mma (inputs pre-rounded -> no cvt in the hot loop).
// A tile stored [m][k] (row-major chunks), B tile stored [k][n].
// ============================================================================
__global__ __launch_bounds__(256, 2) void k_out_tc(float* __restrict__ out)
{
    __shared__ float sA[2][128][20];   // [m][k], pad to 20 floats
    __shared__ float sB[2][16][136];   // [k][n], pad to 136 floats

    const int b  = blockIdx.z;
    const int i0 = blockIdx.y * 128;
    const int o0 = blockIdx.x * 128;
    const int tid  = threadIdx.x;
    const int lane = tid & 31;
    const int wid  = tid >> 5;
    const int m0w  = (wid >> 2) * 64;
    const int n0w  = (wid & 3) * 32;

    const float* A  = g_attn + (size_t)b * NNODE * NNODE;
    const float* Bm = g_Wh   + (size_t)b * NNODE * FEAT;

    float acc[4][4][4];
#pragma unroll
    for (int i = 0; i < 4; i++)
#pragma unroll
        for (int j = 0; j < 4; j++)
#pragma unroll
            for (int r = 0; r < 4; r++) acc[i][j][r] = 0.f;

    const int T = NNODE / 16;  // 64

    auto load_stage = [&](int buf, int k0) {
#pragma unroll
        for (int it = 0; it < 2; it++) {
            int f = tid + it * 256;      // 0..511
            // A: 128 rows x 16 k
            int row = f >> 2;
            int kq  = (f & 3) * 4;
            cp16((uint32_t)__cvta_generic_to_shared(&sA[buf][row][kq]),
                 A + (size_t)(i0 + row) * NNODE + k0 + kq);
            // B: 16 k-rows x 128 n
            int kr = f >> 5;
            int nc = (f & 31) * 4;
            cp16((uint32_t)__cvta_generic_to_shared(&sB[buf][kr][nc]),
                 Bm + (size_t)(k0 + kr) * FEAT + o0 + nc);
        }
    };

    load_stage(0, 0);
    cp_commit();

    for (int t = 0; t < T; t++) {
        if (t + 1 < T) { load_stage((t + 1) & 1, (t + 1) * 16); cp_commit(); }
        if (t + 1 < T) cp_wait1(); else cp_wait0();
        __syncthreads();

        const int buf = t & 1;
#pragma unroll
        for (int kk = 0; kk < 16; kk += 8) {
            uint32_t a[4][4];
#pragma unroll
            for (int mi = 0; mi < 4; mi++) {
                int r = m0w + mi * 16 + (lane >> 2);
                a[mi][0] = __float_as_uint(sA[buf][r    ][kk + (lane & 3)    ]);
                a[mi][1] = __float_as_uint(sA[buf][r + 8][kk + (lane & 3)    ]);
                a[mi][2] = __float_as_uint(sA[buf][r    ][kk + (lane & 3) + 4]);
                a[mi][3] = __float_as_uint(sA[buf][r + 8][kk + (lane & 3) + 4]);
            }
            uint32_t bf[4][2];
#pragma unroll
            for (int nj = 0; nj < 4; nj++) {
                int c = n0w + nj * 8 + (lane >> 2);
                bf[nj][0] = __float_as_uint(sB[buf][kk + (lane & 3)    ][c]);
                bf[nj][1] = __float_as_uint(sB[buf][kk + (lane & 3) + 4][c]);
            }
#pragma unroll
            for (int mi = 0; mi < 4; mi++)
#pragma unroll
                for (int nj = 0; nj < 4; nj++)
                    mma_tf32(acc[mi][nj], a[mi], bf[nj]);
        }
        __syncthreads();
    }

    // ELU epilogue + store
#pragma unroll
    for (int mi = 0; mi < 4; mi++) {
#pragma unroll
        for (int nj = 0; nj < 4; nj++) {
            int row = i0 + m0w + mi * 16 + (lane >> 2);
            int col = o0 + n0w + nj * 8 + 2 * (lane & 3);
            float v0 = acc[mi][nj][0], v1 = acc[mi][nj][1];
            float v2 = acc[mi][nj][2], v3 = acc[mi][nj][3];
            v0 = (v0 > 0.f) ? v0 : expm1f(v0);
            v1 = (v1 > 0.f) ? v1 : expm1f(v1);
            v2 = (v2 > 0.f) ? v2 : expm1f(v2);
            v3 = (v3 > 0.f) ? v3 : expm1f(v3);
            size_t base = (size_t)(b * NNODE + row) * FEAT + col;
            *(float2*)(out + base)               = make_float2(v0, v1);
            *(float2*)(out + base + 8 * FEAT)    = make_float2(v2, v3);
        }
    }
}

// ============================================================================
// launch
// ============================================================================
extern "C" void kernel_launch(void* const* d_in, const int* in_sizes, int n_in,
                              void* d_out, int out_size)
{
    const float* h   = (const float*)d_in[0];
    const int*   adj = (const int*)  d_in[1];
    const float* W   = (const float*)d_in[2];
    const float* a   = (const float*)d_in[3];
    float*       out = (float*)d_out;

    // K1: Wh = h @ W^T (tensor cores, tf32)
    {
        dim3 grid(FEAT / 128, MROWS / 128);   // (2, 256)
        k_wh_tc<<<grid, 256>>>(h, W);
    }
    // K2: si, sj
    k_sisj<<<MROWS / 8, 256>>>(a);
    // K3: masked leaky-relu softmax -> attn (tf32-rounded)
    k_softmax<<<MROWS, 256>>>(adj);
    // K4: out = elu(attn @ Wh) (tensor cores, tf32)
    {
        dim3 grid(FEAT / 128, NNODE / 128, BATCH);  // (2, 8, 32)
        k_out_tc<<<grid, 256>>>(out);
    }
}

// round 3
// speedup vs baseline: 2.8015x; 1.2072x over previous
#include <cuda_runtime.h>
#include <cuda_bf16.h>
#include <math.h>
#include <stdint.h>

// Problem constants
#define BATCH 32
#define NNODE 1024
#define FEAT  256           // IN_F == OUT_F == 256
#define MROWS (BATCH*NNODE) // 32768
#define ALPHA_LRELU 0.2f

// ---------------- scratch (device globals; no runtime allocation) -----------
__device__ float g_Wh[(size_t)MROWS * FEAT];                 // 32 MB (tf32-rounded)
__device__ float g_si[MROWS];
__device__ float g_sj[MROWS];

// ---------------- helpers ----------------------------------------------------
__device__ __forceinline__ float to_tf32(float x) {
    float r;
    asm("cvt.rna.tf32.f32 %0, %1;" : "=f"(r) : "f"(x));
    return r;
}

__device__ __forceinline__ void cp16(uint32_t dst, const void* src) {
    asm volatile("cp.async.cg.shared.global [%0], [%1], 16;\n" :: "r"(dst), "l"(src));
}
__device__ __forceinline__ void cp_commit() {
    asm volatile("cp.async.commit_group;\n" ::);
}
__device__ __forceinline__ void cp_wait1() {
    asm volatile("cp.async.wait_group 1;\n" ::);
}
__device__ __forceinline__ void cp_wait0() {
    asm volatile("cp.async.wait_group 0;\n" ::);
}

__device__ __forceinline__ void mma_tf32(float* c, const uint32_t* a, const uint32_t* b) {
    asm volatile(
        "mma.sync.aligned.m16n8k8.row.col.f32.tf32.tf32.f32 "
        "{%0,%1,%2,%3}, {%4,%5,%6,%7}, {%8,%9}, {%0,%1,%2,%3};"
        : "+f"(c[0]), "+f"(c[1]), "+f"(c[2]), "+f"(c[3])
        : "r"(a[0]), "r"(a[1]), "r"(a[2]), "r"(a[3]), "r"(b[0]), "r"(b[1]));
}

// ============================================================================
// K1: Wh[m,o] = sum_k h[m,k] * W[o,k]   (NT GEMM, M=32768, N=256, K=256)
// tf32 mma, 128x128 CTA tile, BK=16, double-buffered cp.async.
// Stores tf32-rounded values into g_Wh.
// ============================================================================
__global__ __launch_bounds__(256, 2) void k_wh_tc(const float* __restrict__ A,
                                                  const float* __restrict__ Bw)
{
    __shared__ float sA[2][128][20];
    __shared__ float sW[2][128][20];

    const int m0 = blockIdx.y * 128;
    const int n0 = blockIdx.x * 128;
    const int tid  = threadIdx.x;
    const int lane = tid & 31;
    const int wid  = tid >> 5;
    const int m0w  = (wid >> 2) * 64;   // 0 or 64
    const int n0w  = (wid & 3) * 32;    // 0,32,64,96

    float acc[4][4][4];
#pragma unroll
    for (int i = 0; i < 4; i++)
#pragma unroll
        for (int j = 0; j < 4; j++)
#pragma unroll
            for (int r = 0; r < 4; r++) acc[i][j][r] = 0.f;

    const int T = FEAT / 16;  // 16

    auto load_stage = [&](int buf, int k0) {
#pragma unroll
        for (int it = 0; it < 2; it++) {
            int f   = tid + it * 256;    // 0..511
            int row = f >> 2;
            int kq  = (f & 3) * 4;
            cp16((uint32_t)__cvta_generic_to_shared(&sA[buf][row][kq]),
                 A + (size_t)(m0 + row) * FEAT + k0 + kq);
            cp16((uint32_t)__cvta_generic_to_shared(&sW[buf][row][kq]),
                 Bw + (size_t)(n0 + row) * FEAT + k0 + kq);
        }
    };

    load_stage(0, 0);
    cp_commit();

    for (int t = 0; t < T; t++) {
        if (t + 1 < T) { load_stage((t + 1) & 1, (t + 1) * 16); cp_commit(); }
        if (t + 1 < T) cp_wait1(); else cp_wait0();
        __syncthreads();

        const int buf = t & 1;
#pragma unroll
        for (int kk = 0; kk < 16; kk += 8) {
            uint32_t a[4][4];
#pragma unroll
            for (int mi = 0; mi < 4; mi++) {
                int r = m0w + mi * 16 + (lane >> 2);
                a[mi][0] = __float_as_uint(to_tf32(sA[buf][r    ][kk + (lane & 3)    ]));
                a[mi][1] = __float_as_uint(to_tf32(sA[buf][r + 8][kk + (lane & 3)    ]));
                a[mi][2] = __float_as_uint(to_tf32(sA[buf][r    ][kk + (lane & 3) + 4]));
                a[mi][3] = __float_as_uint(to_tf32(sA[buf][r + 8][kk + (lane & 3) + 4]));
            }
            uint32_t bf[4][2];
#pragma unroll
            for (int nj = 0; nj < 4; nj++) {
                int c = n0w + nj * 8 + (lane >> 2);
                bf[nj][0] = __float_as_uint(to_tf32(sW[buf][c][kk + (lane & 3)    ]));
                bf[nj][1] = __float_as_uint(to_tf32(sW[buf][c][kk + (lane & 3) + 4]));
            }
#pragma unroll
            for (int mi = 0; mi < 4; mi++)
#pragma unroll
                for (int nj = 0; nj < 4; nj++)
                    mma_tf32(acc[mi][nj], a[mi], bf[nj]);
        }
        __syncthreads();
    }

#pragma unroll
    for (int mi = 0; mi < 4; mi++) {
#pragma unroll
        for (int nj = 0; nj < 4; nj++) {
            int row = m0 + m0w + mi * 16 + (lane >> 2);
            int col = n0 + n0w + nj * 8 + 2 * (lane & 3);
            float2 v0 = make_float2(to_tf32(acc[mi][nj][0]), to_tf32(acc[mi][nj][1]));
            float2 v1 = make_float2(to_tf32(acc[mi][nj][2]), to_tf32(acc[mi][nj][3]));
            *(float2*)(g_Wh + (size_t)row * FEAT + col)       = v0;
            *(float2*)(g_Wh + (size_t)(row + 8) * FEAT + col) = v1;
        }
    }
}

// ============================================================================
// K2: si = Wh @ a1, sj = Wh @ a2  (one warp per row)
// ============================================================================
__global__ __launch_bounds__(256) void k_sisj(const float* __restrict__ a)
{
    int row  = blockIdx.x * 8 + (threadIdx.x >> 5);
    int lane = threadIdx.x & 31;
    const float* w = g_Wh + (size_t)row * FEAT;
    float d1 = 0.f, d2 = 0.f;
#pragma unroll
    for (int u = 0; u < 8; u++) {
        int k = lane + u * 32;
        float v = w[k];
        d1 += v * a[k];
        d2 += v * a[FEAT + k];
    }
#pragma unroll
    for (int s = 16; s > 0; s >>= 1) {
        d1 += __shfl_xor_sync(0xffffffff, d1, s);
        d2 += __shfl_xor_sync(0xffffffff, d2, s);
    }
    if (lane == 0) { g_si[row] = d1; g_sj[row] = d2; }
}

// ============================================================================
// K3 (fused): for each 64-row i-tile of batch b:
//   E[i,j] = adj>0 ? exp(leaky_relu(si[i]+sj[j])) : 0   (no max pass; args bounded)
//   O[i,:] = (E @ Wh[b]) / rowsum(E), then ELU.
// j-loop in steps of 32, cp.async double-buffered adj+Wh tiles, tf32 MMA.
// CTA tile: 64 x 256 (full OUT_F). 8 warps as 2(m) x 4(n) -> warp 32x64.
// ============================================================================
#define BI 64
#define BJ 32

struct SmemFused {
    float wh[2][BJ][264];    // [k][n] B tiles (pad 264 -> conflict-free frags)
    float e[BI][36];         // A tile (single buffer)
    int   adj[2][BI][BJ];
    float sj[NNODE];
    float rs[BI];
};

__global__ __launch_bounds__(256, 2) void k_fused(const int* __restrict__ adj,
                                                  float* __restrict__ out)
{
    extern __shared__ char smem_raw[];
    SmemFused* s = (SmemFused*)smem_raw;

    const int b  = blockIdx.y;
    const int i0 = blockIdx.x * BI;
    const int tid  = threadIdx.x;
    const int lane = tid & 31;
    const int wid  = tid >> 5;
    const int m0w  = (wid >> 2) * 32;   // 0 or 32
    const int n0w  = (wid & 3) * 64;    // 0,64,128,192

    const int*   adjb = adj  + ((size_t)b * NNODE + i0) * NNODE;
    const float* Whb  = g_Wh + (size_t)b * NNODE * FEAT;

    // preload sj for this batch (1024 floats) + per-thread si
    {
        float4 v = *(const float4*)(g_sj + (size_t)b * NNODE + tid * 4);
        *(float4*)&s->sj[tid * 4] = v;
    }
    const int   erow = tid >> 2;            // E row this thread produces
    const int   ecol = (tid & 3) * 8;       // first of 8 E cols
    const float si_r = g_si[(size_t)b * NNODE + i0 + erow];

    float acc[2][8][4];
#pragma unroll
    for (int i = 0; i < 2; i++)
#pragma unroll
        for (int j = 0; j < 8; j++)
#pragma unroll
            for (int r = 0; r < 4; r++) acc[i][j][r] = 0.f;

    float esum = 0.f;

    auto load_stage = [&](int buf, int j0) {
        // adj tile: 64 x 32 ints = 512 cp16 -> 2/thread
#pragma unroll
        for (int it = 0; it < 2; it++) {
            int f   = tid + it * 256;
            int row = f >> 3;
            int c   = (f & 7) * 4;
            cp16((uint32_t)__cvta_generic_to_shared(&s->adj[buf][row][c]),
                 adjb + (size_t)row * NNODE + j0 + c);
        }
        // Wh tile: 32 x 256 floats = 2048 cp16 -> 8/thread
#pragma unroll
        for (int it = 0; it < 8; it++) {
            int f = tid + it * 256;
            int k = f >> 6;
            int c = (f & 63) * 4;
            cp16((uint32_t)__cvta_generic_to_shared(&s->wh[buf][k][c]),
                 Whb + (size_t)(j0 + k) * FEAT + c);
        }
    };

    load_stage(0, 0);
    cp_commit();

    const int T = NNODE / BJ;  // 32
    for (int t = 0; t < T; t++) {
        const int buf = t & 1;
        cp_wait0();
        __syncthreads();                       // stage t ready; prev MMA done

        if (t + 1 < T) { load_stage(buf ^ 1, (t + 1) * BJ); cp_commit(); }

        // compute E tile (64 x 32): this thread -> row erow, cols ecol..ecol+7
        {
            const int j0 = t * BJ;
            float ev[8];
#pragma unroll
            for (int u = 0; u < 8; u++) {
                int jc = ecol + u;
                float x = si_r + s->sj[j0 + jc];
                x = (x >= 0.f) ? x : ALPHA_LRELU * x;
                float e = (s->adj[buf][erow][jc] > 0) ? __expf(x) : 0.f;
                e = to_tf32(e);
                esum += e;
                ev[u] = e;
            }
            *(float4*)&s->e[erow][ecol]     = make_float4(ev[0], ev[1], ev[2], ev[3]);
            *(float4*)&s->e[erow][ecol + 4] = make_float4(ev[4], ev[5], ev[6], ev[7]);
        }
        __syncthreads();                       // E visible to all warps

        // MMA: 64x256 += E(64x32) @ Wh(32x256)
#pragma unroll
        for (int kk = 0; kk < BJ; kk += 8) {
            uint32_t a[2][4];
#pragma unroll
            for (int mi = 0; mi < 2; mi++) {
                int r = m0w + mi * 16 + (lane >> 2);
                a[mi][0] = __float_as_uint(s->e[r    ][kk + (lane & 3)    ]);
                a[mi][1] = __float_as_uint(s->e[r + 8][kk + (lane & 3)    ]);
                a[mi][2] = __float_as_uint(s->e[r    ][kk + (lane & 3) + 4]);
                a[mi][3] = __float_as_uint(s->e[r + 8][kk + (lane & 3) + 4]);
            }
            uint32_t bf[8][2];
#pragma unroll
            for (int nj = 0; nj < 8; nj++) {
                int c = n0w + nj * 8 + (lane >> 2);
                bf[nj][0] = __float_as_uint(s->wh[buf][kk + (lane & 3)    ][c]);
                bf[nj][1] = __float_as_uint(s->wh[buf][kk + (lane & 3) + 4][c]);
            }
#pragma unroll
            for (int mi = 0; mi < 2; mi++)
#pragma unroll
                for (int nj = 0; nj < 8; nj++)
                    mma_tf32(acc[mi][nj], a[mi], bf[nj]);
        }
    }

    // rowsum reduce: 4 threads (same erow) hold partials; quad lanes aligned
    esum += __shfl_xor_sync(0xffffffff, esum, 1);
    esum += __shfl_xor_sync(0xffffffff, esum, 2);
    __syncthreads();
    if ((tid & 3) == 0) s->rs[erow] = esum;
    __syncthreads();

    // epilogue: normalize, ELU, store
#pragma unroll
    for (int mi = 0; mi < 2; mi++) {
        int r0 = m0w + mi * 16 + (lane >> 2);
        float inv0 = 1.f / s->rs[r0];
        float inv1 = 1.f / s->rs[r0 + 8];
#pragma unroll
        for (int nj = 0; nj < 8; nj++) {
            int col = n0w + nj * 8 + 2 * (lane & 3);
            float v0 = acc[mi][nj][0] * inv0, v1 = acc[mi][nj][1] * inv0;
            float v2 = acc[mi][nj][2] * inv1, v3 = acc[mi][nj][3] * inv1;
            v0 = (v0 > 0.f) ? v0 : expm1f(v0);
            v1 = (v1 > 0.f) ? v1 : expm1f(v1);
            v2 = (v2 > 0.f) ? v2 : expm1f(v2);
            v3 = (v3 > 0.f) ? v3 : expm1f(v3);
            size_t base = (size_t)(b * NNODE + i0 + r0) * FEAT + col;
            *(float2*)(out + base)            = make_float2(v0, v1);
            *(float2*)(out + base + 8 * FEAT) = make_float2(v2, v3);
        }
    }
}

// ============================================================================
// launch
// ============================================================================
extern "C" void kernel_launch(void* const* d_in, const int* in_sizes, int n_in,
                              void* d_out, int out_size)
{
    const float* h   = (const float*)d_in[0];
    const int*   adj = (const int*)  d_in[1];
    const float* W   = (const float*)d_in[2];
    const float* a   = (const float*)d_in[3];
    float*       out = (float*)d_out;

    // K1: Wh = h @ W^T (tensor cores, tf32)
    {
        dim3 grid(FEAT / 128, MROWS / 128);   // (2, 256)
        k_wh_tc<<<grid, 256>>>(h, W);
    }
    // K2: si, sj
    k_sisj<<<MROWS / 8, 256>>>(a);
    // K3: fused masked-softmax + attn@Wh + ELU
    {
        cudaFuncSetAttribute(k_fused, cudaFuncAttributeMaxDynamicSharedMemorySize,
                             (int)sizeof(SmemFused));
        dim3 grid(NNODE / BI, BATCH);         // (16, 32)
        k_fused<<<grid, 256, sizeof(SmemFused)>>>(adj, out);
    }
}

// round 4
// speedup vs baseline: 3.0126x; 1.0754x over previous
#include <cuda_runtime.h>
#include <cuda_bf16.h>
#include <math.h>
#include <stdint.h>

// Problem constants
#define BATCH 32
#define NNODE 1024
#define FEAT  256           // IN_F == OUT_F == 256
#define MROWS (BATCH*NNODE) // 32768
#define ALPHA_LRELU 0.2f

// ---------------- scratch (device globals; no runtime allocation) -----------
__device__ float g_Wh[(size_t)MROWS * FEAT];                 // 32 MB (tf32-rounded)
__device__ float g_si[MROWS];
__device__ float g_sj[MROWS];

// ---------------- helpers ----------------------------------------------------
__device__ __forceinline__ float to_tf32(float x) {
    float r;
    asm("cvt.rna.tf32.f32 %0, %1;" : "=f"(r) : "f"(x));
    return r;
}

__device__ __forceinline__ void cp16(uint32_t dst, const void* src) {
    asm volatile("cp.async.cg.shared.global [%0], [%1], 16;\n" :: "r"(dst), "l"(src));
}
__device__ __forceinline__ void cp_commit() {
    asm volatile("cp.async.commit_group;\n" ::);
}
__device__ __forceinline__ void cp_wait1() {
    asm volatile("cp.async.wait_group 1;\n" ::);
}
__device__ __forceinline__ void cp_wait0() {
    asm volatile("cp.async.wait_group 0;\n" ::);
}

__device__ __forceinline__ void mma_tf32(float* c, const uint32_t* a, const uint32_t* b) {
    asm volatile(
        "mma.sync.aligned.m16n8k8.row.col.f32.tf32.tf32.f32 "
        "{%0,%1,%2,%3}, {%4,%5,%6,%7}, {%8,%9}, {%0,%1,%2,%3};"
        : "+f"(c[0]), "+f"(c[1]), "+f"(c[2]), "+f"(c[3])
        : "r"(a[0]), "r"(a[1]), "r"(a[2]), "r"(a[3]), "r"(b[0]), "r"(b[1]));
}

// ============================================================================
// K1: Wh[m,o] = sum_k h[m,k] * W[o,k]   (NT GEMM, M=32768, N=256, K=256)
// tf32 mma, 128x128 CTA tile, BK=16, double-buffered cp.async.
// Stores tf32-rounded values into g_Wh.
// ============================================================================
__global__ __launch_bounds__(256, 2) void k_wh_tc(const float* __restrict__ A,
                                                  const float* __restrict__ Bw)
{
    __shared__ float sA[2][128][20];
    __shared__ float sW[2][128][20];

    const int m0 = blockIdx.y * 128;
    const int n0 = blockIdx.x * 128;
    const int tid  = threadIdx.x;
    const int lane = tid & 31;
    const int wid  = tid >> 5;
    const int m0w  = (wid >> 2) * 64;   // 0 or 64
    const int n0w  = (wid & 3) * 32;    // 0,32,64,96

    float acc[4][4][4];
#pragma unroll
    for (int i = 0; i < 4; i++)
#pragma unroll
        for (int j = 0; j < 4; j++)
#pragma unroll
            for (int r = 0; r < 4; r++) acc[i][j][r] = 0.f;

    const int T = FEAT / 16;  // 16

    auto load_stage = [&](int buf, int k0) {
#pragma unroll
        for (int it = 0; it < 2; it++) {
            int f   = tid + it * 256;    // 0..511
            int row = f >> 2;
            int kq  = (f & 3) * 4;
            cp16((uint32_t)__cvta_generic_to_shared(&sA[buf][row][kq]),
                 A + (size_t)(m0 + row) * FEAT + k0 + kq);
            cp16((uint32_t)__cvta_generic_to_shared(&sW[buf][row][kq]),
                 Bw + (size_t)(n0 + row) * FEAT + k0 + kq);
        }
    };

    load_stage(0, 0);
    cp_commit();

    for (int t = 0; t < T; t++) {
        if (t + 1 < T) { load_stage((t + 1) & 1, (t + 1) * 16); cp_commit(); }
        if (t + 1 < T) cp_wait1(); else cp_wait0();
        __syncthreads();

        const int buf = t & 1;
#pragma unroll
        for (int kk = 0; kk < 16; kk += 8) {
            uint32_t a[4][4];
#pragma unroll
            for (int mi = 0; mi < 4; mi++) {
                int r = m0w + mi * 16 + (lane >> 2);
                a[mi][0] = __float_as_uint(to_tf32(sA[buf][r    ][kk + (lane & 3)    ]));
                a[mi][1] = __float_as_uint(to_tf32(sA[buf][r + 8][kk + (lane & 3)    ]));
                a[mi][2] = __float_as_uint(to_tf32(sA[buf][r    ][kk + (lane & 3) + 4]));
                a[mi][3] = __float_as_uint(to_tf32(sA[buf][r + 8][kk + (lane & 3) + 4]));
            }
            uint32_t bf[4][2];
#pragma unroll
            for (int nj = 0; nj < 4; nj++) {
                int c = n0w + nj * 8 + (lane >> 2);
                bf[nj][0] = __float_as_uint(to_tf32(sW[buf][c][kk + (lane & 3)    ]));
                bf[nj][1] = __float_as_uint(to_tf32(sW[buf][c][kk + (lane & 3) + 4]));
            }
#pragma unroll
            for (int mi = 0; mi < 4; mi++)
#pragma unroll
                for (int nj = 0; nj < 4; nj++)
                    mma_tf32(acc[mi][nj], a[mi], bf[nj]);
        }
        __syncthreads();
    }

#pragma unroll
    for (int mi = 0; mi < 4; mi++) {
#pragma unroll
        for (int nj = 0; nj < 4; nj++) {
            int row = m0 + m0w + mi * 16 + (lane >> 2);
            int col = n0 + n0w + nj * 8 + 2 * (lane & 3);
            float2 v0 = make_float2(to_tf32(acc[mi][nj][0]), to_tf32(acc[mi][nj][1]));
            float2 v1 = make_float2(to_tf32(acc[mi][nj][2]), to_tf32(acc[mi][nj][3]));
            *(float2*)(g_Wh + (size_t)row * FEAT + col)       = v0;
            *(float2*)(g_Wh + (size_t)(row + 8) * FEAT + col) = v1;
        }
    }
}

// ============================================================================
// K2: si = Wh @ a1, sj = Wh @ a2  (one warp per row)
// ============================================================================
__global__ __launch_bounds__(256) void k_sisj(const float* __restrict__ a)
{
    int row  = blockIdx.x * 8 + (threadIdx.x >> 5);
    int lane = threadIdx.x & 31;
    const float* w = g_Wh + (size_t)row * FEAT;
    float d1 = 0.f, d2 = 0.f;
#pragma unroll
    for (int u = 0; u < 8; u++) {
        int k = lane + u * 32;
        float v = w[k];
        d1 += v * a[k];
        d2 += v * a[FEAT + k];
    }
#pragma unroll
    for (int s = 16; s > 0; s >>= 1) {
        d1 += __shfl_xor_sync(0xffffffff, d1, s);
        d2 += __shfl_xor_sync(0xffffffff, d2, s);
    }
    if (lane == 0) { g_si[row] = d1; g_sj[row] = d2; }
}

// ============================================================================
// K3 (fused, pipelined): for each 64-row i-tile of batch b:
//   E[i,j] = adj>0 ? exp(leaky_relu(si[i]+sj[j])) : 0
//   O[i,:] = (E @ Wh[b]) / rowsum(E), then ELU.
// Software pipeline with ONE __syncthreads per j-step:
//   iter t: [commit G_{t+1}={Wh(t+1), adj(t+2)}] ; wait G_t ;
//           MMA(t) on e[t&1] x wh[t&1]  +  E-compute(t+1) -> e[(t+1)&1] ; bar
// ============================================================================
#define BI 64
#define BJ 32

struct SmemFused {
    float wh[2][BJ][264];    // [k][n] B tiles
    float e[2][BI][36];      // E tiles, double-buffered
    int   adj[2][BI][BJ];
    float sj[NNODE];
    float rs[BI];
};

__global__ __launch_bounds__(256, 2) void k_fused(const int* __restrict__ adj,
                                                  float* __restrict__ out)
{
    extern __shared__ char smem_raw[];
    SmemFused* s = (SmemFused*)smem_raw;

    const int b  = blockIdx.y;
    const int i0 = blockIdx.x * BI;
    const int tid  = threadIdx.x;
    const int lane = tid & 31;
    const int wid  = tid >> 5;
    const int m0w  = (wid >> 2) * 32;   // 0 or 32
    const int n0w  = (wid & 3) * 64;    // 0,64,128,192

    const int*   adjb = adj  + ((size_t)b * NNODE + i0) * NNODE;
    const float* Whb  = g_Wh + (size_t)b * NNODE * FEAT;

    // preload sj for this batch (1024 floats) + per-thread si
    {
        float4 v = *(const float4*)(g_sj + (size_t)b * NNODE + tid * 4);
        *(float4*)&s->sj[tid * 4] = v;
    }
    const int   erow = tid >> 2;            // E row this thread produces
    const int   ecol = (tid & 3) * 8;       // first of 8 E cols
    const float si_r = g_si[(size_t)b * NNODE + i0 + erow];

    float acc[2][8][4];
#pragma unroll
    for (int i = 0; i < 2; i++)
#pragma unroll
        for (int j = 0; j < 8; j++)
#pragma unroll
            for (int r = 0; r < 4; r++) acc[i][j][r] = 0.f;

    float esum = 0.f;

    auto load_adj = [&](int buf, int j0) {
#pragma unroll
        for (int it = 0; it < 2; it++) {
            int f   = tid + it * 256;
            int row = f >> 3;
            int c   = (f & 7) * 4;
            cp16((uint32_t)__cvta_generic_to_shared(&s->adj[buf][row][c]),
                 adjb + (size_t)row * NNODE + j0 + c);
        }
    };
    auto load_wh = [&](int buf, int j0) {
#pragma unroll
        for (int it = 0; it < 8; it++) {
            int f = tid + it * 256;
            int k = f >> 6;
            int c = (f & 63) * 4;
            cp16((uint32_t)__cvta_generic_to_shared(&s->wh[buf][k][c]),
                 Whb + (size_t)(j0 + k) * FEAT + c);
        }
    };

    const int T = NNODE / BJ;  // 32

    // Preamble: G_a = {adj(0)}, G_0 = {wh(0), adj(1)}
    load_adj(0, 0);
    cp_commit();
    load_wh(0, 0);
    load_adj(1, BJ);
    cp_commit();
    cp_wait1();          // adj(0) arrived
    __syncthreads();

    // E(0) -> e[0]
    {
        float ev[8];
#pragma unroll
        for (int u = 0; u < 8; u++) {
            int jc = ecol + u;
            float x = si_r + s->sj[jc];
            x = (x >= 0.f) ? x : ALPHA_LRELU * x;
            float e = (s->adj[0][erow][jc] > 0) ? __expf(x) : 0.f;
            e = to_tf32(e);
            esum += e;
            ev[u] = e;
        }
        *(float4*)&s->e[0][erow][ecol]     = make_float4(ev[0], ev[1], ev[2], ev[3]);
        *(float4*)&s->e[0][erow][ecol + 4] = make_float4(ev[4], ev[5], ev[6], ev[7]);
    }
    __syncthreads();

    for (int t = 0; t < T; t++) {
        const int buf = t & 1;

        // Commit G_{t+1} = {wh(t+1), adj(t+2)}
        if (t + 1 < T) {
            load_wh(buf ^ 1, (t + 1) * BJ);
            if (t + 2 < T) load_adj(buf, (t + 2) * BJ);
            cp_commit();
            cp_wait1();        // G_t arrived: wh(t) + adj(t+1)
        } else {
            cp_wait0();
        }

        // ---- MMA(t): 64x256 += E(t) @ Wh(t) ----
#pragma unroll
        for (int kk = 0; kk < BJ; kk += 8) {
            uint32_t a[2][4];
#pragma unroll
            for (int mi = 0; mi < 2; mi++) {
                int r = m0w + mi * 16 + (lane >> 2);
                a[mi][0] = __float_as_uint(s->e[buf][r    ][kk + (lane & 3)    ]);
                a[mi][1] = __float_as_uint(s->e[buf][r + 8][kk + (lane & 3)    ]);
                a[mi][2] = __float_as_uint(s->e[buf][r    ][kk + (lane & 3) + 4]);
                a[mi][3] = __float_as_uint(s->e[buf][r + 8][kk + (lane & 3) + 4]);
            }
            uint32_t bf[8][2];
#pragma unroll
            for (int nj = 0; nj < 8; nj++) {
                int c = n0w + nj * 8 + (lane >> 2);
                bf[nj][0] = __float_as_uint(s->wh[buf][kk + (lane & 3)    ][c]);
                bf[nj][1] = __float_as_uint(s->wh[buf][kk + (lane & 3) + 4][c]);
            }
#pragma unroll
            for (int mi = 0; mi < 2; mi++)
#pragma unroll
                for (int nj = 0; nj < 8; nj++)
                    mma_tf32(acc[mi][nj], a[mi], bf[nj]);
        }

        // ---- E-compute(t+1) -> e[buf^1] (overlaps with HMMA drain) ----
        if (t + 1 < T) {
            const int j0 = (t + 1) * BJ;
            float ev[8];
#pragma unroll
            for (int u = 0; u < 8; u++) {
                int jc = ecol + u;
                float x = si_r + s->sj[j0 + jc];
                x = (x >= 0.f) ? x : ALPHA_LRELU * x;
                float e = (s->adj[buf ^ 1][erow][jc] > 0) ? __expf(x) : 0.f;
                e = to_tf32(e);
                esum += e;
                ev[u] = e;
            }
            *(float4*)&s->e[buf ^ 1][erow][ecol]     = make_float4(ev[0], ev[1], ev[2], ev[3]);
            *(float4*)&s->e[buf ^ 1][erow][ecol + 4] = make_float4(ev[4], ev[5], ev[6], ev[7]);
        }

        __syncthreads();   // single barrier per iteration
    }

    // rowsum reduce: 4 threads (same erow) hold partials
    esum += __shfl_xor_sync(0xffffffff, esum, 1);
    esum += __shfl_xor_sync(0xffffffff, esum, 2);
    if ((tid & 3) == 0) s->rs[erow] = esum;
    __syncthreads();

    // epilogue: normalize, ELU, store
#pragma unroll
    for (int mi = 0; mi < 2; mi++) {
        int r0 = m0w + mi * 16 + (lane >> 2);
        float inv0 = 1.f / s->rs[r0];
        float inv1 = 1.f / s->rs[r0 + 8];
#pragma unroll
        for (int nj = 0; nj < 8; nj++) {
            int col = n0w + nj * 8 + 2 * (lane & 3);
            float v0 = acc[mi][nj][0] * inv0, v1 = acc[mi][nj][1] * inv0;
            float v2 = acc[mi][nj][2] * inv1, v3 = acc[mi][nj][3] * inv1;
            v0 = (v0 > 0.f) ? v0 : expm1f(v0);
            v1 = (v1 > 0.f) ? v1 : expm1f(v1);
            v2 = (v2 > 0.f) ? v2 : expm1f(v2);
            v3 = (v3 > 0.f) ? v3 : expm1f(v3);
            size_t base = (size_t)(b * NNODE + i0 + r0) * FEAT + col;
            *(float2*)(out + base)            = make_float2(v0, v1);
            *(float2*)(out + base + 8 * FEAT) = make_float2(v2, v3);
        }
    }
}

// ============================================================================
// launch
// ============================================================================
extern "C" void kernel_launch(void* const* d_in, const int* in_sizes, int n_in,
                              void* d_out, int out_size)
{
    const float* h   = (const float*)d_in[0];
    const int*   adj = (const int*)  d_in[1];
    const float* W   = (const float*)d_in[2];
    const float* a   = (const float*)d_in[3];
    float*       out = (float*)d_out;

    // K1: Wh = h @ W^T (tensor cores, tf32)
    {
        dim3 grid(FEAT / 128, MROWS / 128);   // (2, 256)
        k_wh_tc<<<grid, 256>>>(h, W);
    }
    // K2: si, sj
    k_sisj<<<MROWS / 8, 256>>>(a);
    // K3: fused masked-softmax + attn@Wh + ELU (pipelined)
    {
        cudaFuncSetAttribute(k_fused, cudaFuncAttributeMaxDynamicSharedMemorySize,
                             (int)sizeof(SmemFused));
        dim3 grid(NNODE / BI, BATCH);         // (16, 32)
        k_fused<<<grid, 256, sizeof(SmemFused)>>>(adj, out);
    }
}